// round 1
// baseline (speedup 1.0000x reference)
#include <cuda_runtime.h>
#include <math.h>
#include <stdint.h>

// ---------------------------------------------------------------------------
// Problem constants (fixed shapes for this problem instance)
// ---------------------------------------------------------------------------
#define TT     4096   // total tokens = batch*q_len
#define HH     4096   // hidden dim
#define NHEADS 32
#define NKV    8
#define HD     128
#define BATCH  4
#define QLEN   1024
#define HIST   1024
#define KVLEN  2048
#define WINDOW 1024
#define DKV    (NKV*HD)      // 1024
#define SCALE  0.08838834764831845f   // 1/sqrt(128)

// ---------------------------------------------------------------------------
// Scratch (device globals: allocation-free rule)
// ---------------------------------------------------------------------------
__device__ float g_q[(size_t)TT * HH];    // 64 MB
__device__ float g_k[(size_t)TT * DKV];   // 16 MB
__device__ float g_v[(size_t)TT * DKV];   // 16 MB
__device__ float g_o[(size_t)TT * HH];    // 64 MB

// ---------------------------------------------------------------------------
// SGEMM: C[M,N] = A[M,K] @ B[K,N], 128x128 block tile, 8x8 per thread, BK=8
// ---------------------------------------------------------------------------
__global__ __launch_bounds__(256) void sgemm_kernel(
    int M, int N, int K,
    const float* __restrict__ A, const float* __restrict__ B, float* __restrict__ C)
{
    constexpr int BM = 128, BN = 128, BK = 8, TM = 8, TN = 8;
    __shared__ float As[BK * BM];
    __shared__ float Bs[BK * BN];

    const int tid = threadIdx.x;
    const int bx = blockIdx.x, by = blockIdx.y;

    const int aRow = tid >> 1;          // 0..127
    const int aCol = (tid & 1) * 4;     // 0 or 4
    const int bRow = tid >> 5;          // 0..7
    const int bCol = (tid & 31) * 4;    // 0..124
    const int tRow = (tid >> 4) * TM;
    const int tCol = (tid & 15) * TN;

    const float* Ab = A + (size_t)by * BM * K;
    const float* Bb = B + (size_t)bx * BN;

    float acc[TM][TN];
#pragma unroll
    for (int i = 0; i < TM; i++)
#pragma unroll
        for (int j = 0; j < TN; j++) acc[i][j] = 0.f;

    for (int k0 = 0; k0 < K; k0 += BK) {
        float4 a4 = *(const float4*)(Ab + (size_t)aRow * K + k0 + aCol);
        As[(aCol + 0) * BM + aRow] = a4.x;
        As[(aCol + 1) * BM + aRow] = a4.y;
        As[(aCol + 2) * BM + aRow] = a4.z;
        As[(aCol + 3) * BM + aRow] = a4.w;
        *(float4*)(Bs + bRow * BN + bCol) =
            *(const float4*)(Bb + (size_t)(k0 + bRow) * N + bCol);
        __syncthreads();

#pragma unroll
        for (int kk = 0; kk < BK; ++kk) {
            float ra[TM], rb[TN];
            *(float4*)&ra[0] = *(float4*)&As[kk * BM + tRow];
            *(float4*)&ra[4] = *(float4*)&As[kk * BM + tRow + 4];
            *(float4*)&rb[0] = *(float4*)&Bs[kk * BN + tCol];
            *(float4*)&rb[4] = *(float4*)&Bs[kk * BN + tCol + 4];
#pragma unroll
            for (int i = 0; i < TM; i++)
#pragma unroll
                for (int j = 0; j < TN; j++)
                    acc[i][j] = fmaf(ra[i], rb[j], acc[i][j]);
        }
        __syncthreads();
    }

    float* Cb = C + (size_t)(by * BM + tRow) * N + bx * BN + tCol;
#pragma unroll
    for (int i = 0; i < TM; i++) {
#pragma unroll
        for (int j = 0; j < TN; j += 4) {
            float4 v = make_float4(acc[i][j], acc[i][j + 1], acc[i][j + 2], acc[i][j + 3]);
            *(float4*)(Cb + (size_t)i * N + j) = v;
        }
    }
}

// ---------------------------------------------------------------------------
// RoPE (in-place on projected Q or K buffer). One thread per (token, head, pair).
// ---------------------------------------------------------------------------
__global__ void rope_kernel(float* __restrict__ x, int heads)
{
    int idx = blockIdx.x * blockDim.x + threadIdx.x;
    int total = TT * heads * 64;
    if (idx >= total) return;
    int j  = idx & 63;
    int th = idx >> 6;
    int h  = th % heads;
    int t  = th / heads;
    int pos = HIST + (t & (QLEN - 1));

    float e = (float)(2 * j) * (1.0f / 128.0f);
    float freq = powf(1.0e6f, -e);
    float ang = (float)pos * freq;
    float s, c;
    sincosf(ang, &s, &c);

    size_t base = (size_t)t * heads * HD + (size_t)h * HD + j;
    float x0 = x[base];
    float x1 = x[base + 64];
    x[base]      = x0 * c - x1 * s;
    x[base + 64] = x1 * c + x0 * s;
}

// ---------------------------------------------------------------------------
// Flash-style attention. Block = (q_tile of 64, head, batch), 256 threads.
// K/V tiles of 64 keys; keys p<HIST come from the cache inputs, p>=HIST from
// the freshly projected (and RoPE'd) g_k/g_v. Exactly 17 key tiles per q-tile.
// ---------------------------------------------------------------------------
#define ATTN_SMEM_FLOATS (64*129 + 64*129 + 64*128 + 64*65 + 64)
#define ATTN_SMEM_BYTES  (ATTN_SMEM_FLOATS * 4)

__global__ __launch_bounds__(256) void attn_kernel(
    const float* __restrict__ kcache, const float* __restrict__ vcache)
{
    const int i0  = blockIdx.x * 64;   // query tile start within the sequence
    const int h   = blockIdx.y;
    const int b   = blockIdx.z;
    const int kvh = h >> 2;            // GQA: 4 q-heads per kv-head
    const int tid = threadIdx.x;

    extern __shared__ float sm[];
    float* sQ = sm;                    // [64][129]  (pad kills stride-128 conflicts)
    float* sK = sQ + 64 * 129;         // [64][129]
    float* sV = sK + 64 * 129;         // [64][128]  (float4-aligned rows)
    float* sS = sV + 64 * 128;         // [64][65]
    float* sA = sS + 64 * 65;          // [64]

    // ---- load Q tile ----
#pragma unroll
    for (int it = 0; it < 8; ++it) {
        int idx = it * 256 + tid;          // 2048 float4s
        int r = idx >> 5;
        int d4 = (idx & 31) * 4;
        float4 v = *(const float4*)&g_q[(size_t)(b * QLEN + i0 + r) * HH + h * HD + d4];
        float* dst = &sQ[r * 129 + d4];
        dst[0] = v.x; dst[1] = v.y; dst[2] = v.z; dst[3] = v.w;
    }

    const int sy = tid >> 4, sx = tid & 15;  // 16x16 thread grid: scores & O
    const int row = tid >> 2, l4 = tid & 3;  // softmax: 4 lanes per row

    float m = -3.0e38f, l = 0.f;
    float o[4][8];
#pragma unroll
    for (int r = 0; r < 4; r++)
#pragma unroll
        for (int c = 0; c < 8; c++) o[r][c] = 0.f;

    const int qpos0 = HIST + i0;

    for (int t = 0; t < 17; ++t) {
        const int p0 = i0 + t * 64;
        __syncthreads();   // previous iteration's sS/sV reads complete

        // ---- load K,V tiles ----
#pragma unroll
        for (int it = 0; it < 8; ++it) {
            int idx = it * 256 + tid;
            int r = idx >> 5;
            int d4 = (idx & 31) * 4;
            int p = p0 + r;
            const float *src_k, *src_v;
            if (p < HIST) {
                size_t base = ((size_t)(b * KVLEN + p) * NKV + kvh) * HD + d4;
                src_k = kcache + base;
                src_v = vcache + base;
            } else {
                size_t base = (size_t)(b * QLEN + (p - HIST)) * DKV + kvh * HD + d4;
                src_k = g_k + base;
                src_v = g_v + base;
            }
            float4 kv = *(const float4*)src_k;
            float* kd = &sK[r * 129 + d4];
            kd[0] = kv.x; kd[1] = kv.y; kd[2] = kv.z; kd[3] = kv.w;
            *(float4*)&sV[r * 128 + d4] = *(const float4*)src_v;
        }
        __syncthreads();

        // ---- scores: S[64][64] = Q @ K^T, 4x4 per thread ----
        float acc[4][4];
#pragma unroll
        for (int r = 0; r < 4; r++)
#pragma unroll
            for (int c = 0; c < 4; c++) acc[r][c] = 0.f;

        for (int kk = 0; kk < 128; ++kk) {
            float ra[4], rb[4];
#pragma unroll
            for (int r = 0; r < 4; r++) ra[r] = sQ[(sy * 4 + r) * 129 + kk];
#pragma unroll
            for (int c = 0; c < 4; c++) rb[c] = sK[(sx * 4 + c) * 129 + kk];
#pragma unroll
            for (int r = 0; r < 4; r++)
#pragma unroll
                for (int c = 0; c < 4; c++)
                    acc[r][c] = fmaf(ra[r], rb[c], acc[r][c]);
        }

        // ---- mask + store S ----
#pragma unroll
        for (int r = 0; r < 4; r++) {
            int qp = qpos0 + sy * 4 + r;
#pragma unroll
            for (int c = 0; c < 4; c++) {
                int kp = p0 + sx * 4 + c;
                float s = acc[r][c] * SCALE;
                bool valid = (kp <= qp) && ((qp - kp) < WINDOW);
                sS[(sy * 4 + r) * 65 + sx * 4 + c] = valid ? s : -3.0e38f;
            }
        }
        __syncthreads();

        // ---- online softmax update (4 lanes cooperate per row) ----
        float tm = -3.0e38f;
#pragma unroll
        for (int j = 0; j < 16; j++) tm = fmaxf(tm, sS[row * 65 + l4 * 16 + j]);
        tm = fmaxf(tm, __shfl_xor_sync(0xffffffffu, tm, 1));
        tm = fmaxf(tm, __shfl_xor_sync(0xffffffffu, tm, 2));
        float mnew = fmaxf(m, tm);
        float alpha = __expf(m - mnew);
        float psum = 0.f;
#pragma unroll
        for (int j = 0; j < 16; j++) {
            float p = __expf(sS[row * 65 + l4 * 16 + j] - mnew);
            sS[row * 65 + l4 * 16 + j] = p;
            psum += p;
        }
        psum += __shfl_xor_sync(0xffffffffu, psum, 1);
        psum += __shfl_xor_sync(0xffffffffu, psum, 2);
        l = l * alpha + psum;
        m = mnew;
        if (l4 == 0) sA[row] = alpha;
        __syncthreads();

        // ---- O update: O = O*alpha + P @ V (4 rows x 8 cols per thread) ----
#pragma unroll
        for (int r = 0; r < 4; r++) {
            float a = sA[sy * 4 + r];
#pragma unroll
            for (int c = 0; c < 8; c++) o[r][c] *= a;
        }
        for (int j = 0; j < 64; ++j) {
            float p[4];
#pragma unroll
            for (int r = 0; r < 4; r++) p[r] = sS[(sy * 4 + r) * 65 + j];
            float4 v0 = *(float4*)&sV[j * 128 + sx * 8];
            float4 v1 = *(float4*)&sV[j * 128 + sx * 8 + 4];
            float vv[8] = {v0.x, v0.y, v0.z, v0.w, v1.x, v1.y, v1.z, v1.w};
#pragma unroll
            for (int r = 0; r < 4; r++)
#pragma unroll
                for (int c = 0; c < 8; c++)
                    o[r][c] = fmaf(p[r], vv[c], o[r][c]);
        }
    }

    // ---- finalize: divide by l, write out ----
    __syncthreads();
    if (l4 == 0) sA[row] = 1.0f / l;
    __syncthreads();
#pragma unroll
    for (int r = 0; r < 4; r++) {
        float inv = sA[sy * 4 + r];
        float* dst = &g_o[(size_t)(b * QLEN + i0 + sy * 4 + r) * HH + h * HD + sx * 8];
#pragma unroll
        for (int c = 0; c < 8; c++) dst[c] = o[r][c] * inv;
    }
}

// ---------------------------------------------------------------------------
// Launch
// ---------------------------------------------------------------------------
extern "C" void kernel_launch(void* const* d_in, const int* in_sizes, int n_in,
                              void* d_out, int out_size)
{
    const float* hs = (const float*)d_in[0];
    const float* wq = (const float*)d_in[1];
    const float* wk = (const float*)d_in[2];
    const float* wv = (const float*)d_in[3];
    const float* wo = (const float*)d_in[4];
    const float* kc = (const float*)d_in[5];
    const float* vc = (const float*)d_in[6];

    float *qb, *kb, *vb, *ob;
    cudaGetSymbolAddress((void**)&qb, g_q);
    cudaGetSymbolAddress((void**)&kb, g_k);
    cudaGetSymbolAddress((void**)&vb, g_v);
    cudaGetSymbolAddress((void**)&ob, g_o);

    cudaFuncSetAttribute(attn_kernel, cudaFuncAttributeMaxDynamicSharedMemorySize,
                         ATTN_SMEM_BYTES);

    dim3 gq(HH / 128, TT / 128);     // 32 x 32
    dim3 gkv(DKV / 128, TT / 128);   // 8 x 32

    // QKV projections
    sgemm_kernel<<<gq,  256>>>(TT, HH,  HH, hs, wq, qb);
    sgemm_kernel<<<gkv, 256>>>(TT, DKV, HH, hs, wk, kb);
    sgemm_kernel<<<gkv, 256>>>(TT, DKV, HH, hs, wv, vb);

    // RoPE on Q and new K
    {
        int totq = TT * NHEADS * 64;
        rope_kernel<<<(totq + 255) / 256, 256>>>(qb, NHEADS);
        int totk = TT * NKV * 64;
        rope_kernel<<<(totk + 255) / 256, 256>>>(kb, NKV);
    }

    // Attention
    dim3 ga(QLEN / 64, NHEADS, BATCH);   // 16 x 32 x 4
    attn_kernel<<<ga, 256, ATTN_SMEM_BYTES>>>(kc, vc);

    // Output projection straight into d_out
    sgemm_kernel<<<gq, 256>>>(TT, HH, HH, ob, wo, (float*)d_out);
}

// round 3
// speedup vs baseline: 1.0593x; 1.0593x over previous
#include <cuda_runtime.h>
#include <math.h>
#include <stdint.h>

// ---------------------------------------------------------------------------
// Problem constants
// ---------------------------------------------------------------------------
#define TT     4096
#define HH     4096
#define NHEADS 32
#define NKV    8
#define HD     128
#define BATCH  4
#define QLEN   1024
#define HIST   1024
#define KVLEN  2048
#define WINDOW 1024
#define DKV    (NKV*HD)
#define SCALE  0.08838834764831845f

// ---------------------------------------------------------------------------
// Scratch
// ---------------------------------------------------------------------------
__device__ float g_q[(size_t)TT * HH];
__device__ float g_k[(size_t)TT * DKV];
__device__ float g_v[(size_t)TT * DKV];
__device__ float g_o[(size_t)TT * HH];

// ---------------------------------------------------------------------------
// 3xTF32 tensor-core GEMM: C[M,N] = A[M,K] @ B[K,N]
// CTA tile 128x128x32, 256 threads = 8 warps (4 in M, 2 in N), warp tile 32x64.
// mma.sync.aligned.m16n8k8.row.col.f32.tf32.tf32.f32 with hi/lo compensation:
//   a = ah + al (ah = a with low 13 mantissa bits cleared)
//   a*b ~= ah*bh + ah*bl + al*bh   (error ~2^-21, fp32-grade)
// ---------------------------------------------------------------------------
#define GBM 128
#define GBN 128
#define GBK 32
#define ASTR (GBM + 8)   // smem row stride (floats) -> frag loads conflict-free
#define BSTR (GBN + 8)
#define GEMM_SMEM_FLOATS (2*GBK*ASTR + 2*GBK*BSTR)
#define GEMM_SMEM_BYTES  (GEMM_SMEM_FLOATS * 4)

__device__ __forceinline__ void mma_tf32(float* d, const uint32_t* a, uint32_t b0, uint32_t b1)
{
    asm volatile(
        "mma.sync.aligned.m16n8k8.row.col.f32.tf32.tf32.f32 "
        "{%0,%1,%2,%3}, {%4,%5,%6,%7}, {%8,%9}, {%0,%1,%2,%3};\n"
        : "+f"(d[0]), "+f"(d[1]), "+f"(d[2]), "+f"(d[3])
        : "r"(a[0]), "r"(a[1]), "r"(a[2]), "r"(a[3]), "r"(b0), "r"(b1));
}

__global__ __launch_bounds__(256) void tf32_gemm_kernel(
    int M, int N, int K,
    const float* __restrict__ A, const float* __restrict__ B, float* __restrict__ C)
{
    extern __shared__ float sm[];
    float* Ah = sm;                    // [GBK][ASTR], k-major
    float* Al = Ah + GBK * ASTR;
    float* Bh = Al + GBK * ASTR;       // [GBK][BSTR]
    float* Bl = Bh + GBK * BSTR;

    const int tid  = threadIdx.x;
    const int lane = tid & 31;
    const int wid  = tid >> 5;
    const int wm   = (wid & 3) * 32;   // warp M offset in tile
    const int wn   = (wid >> 2) * 64;  // warp N offset in tile
    const int g    = lane >> 2;        // groupID
    const int tg   = lane & 3;         // threadID_in_group

    const float* Abase = A + (size_t)blockIdx.y * GBM * K;
    const float* Bbase = B + (size_t)blockIdx.x * GBN;

    float acc[2][8][4];
#pragma unroll
    for (int mt = 0; mt < 2; mt++)
#pragma unroll
        for (int nt = 0; nt < 8; nt++)
#pragma unroll
            for (int i = 0; i < 4; i++) acc[mt][nt][i] = 0.f;

    const int am  = tid >> 3;           // 0..31 (plus it*32)
    const int ak  = (tid & 7) * 4;      // 0..28
    const int bk0 = tid >> 5;           // 0..7 (plus it*8)
    const int bn  = (tid & 31) * 4;     // 0..124

    for (int k0 = 0; k0 < K; k0 += GBK) {
        // ---- load & decompose A tile (transpose to k-major) ----
#pragma unroll
        for (int it = 0; it < 4; ++it) {
            int m = it * 32 + am;
            float4 v = *(const float4*)(Abase + (size_t)m * K + k0 + ak);
            float vv[4] = {v.x, v.y, v.z, v.w};
#pragma unroll
            for (int j = 0; j < 4; j++) {
                float a  = vv[j];
                float hi = __uint_as_float(__float_as_uint(a) & 0xFFFFE000u);
                Ah[(ak + j) * ASTR + m] = hi;
                Al[(ak + j) * ASTR + m] = a - hi;
            }
        }
        // ---- load & decompose B tile (no transpose, float4 stores) ----
#pragma unroll
        for (int it = 0; it < 4; ++it) {
            int kk = it * 8 + bk0;
            float4 v = *(const float4*)(Bbase + (size_t)(k0 + kk) * N + bn);
            float4 h, l;
            h.x = __uint_as_float(__float_as_uint(v.x) & 0xFFFFE000u); l.x = v.x - h.x;
            h.y = __uint_as_float(__float_as_uint(v.y) & 0xFFFFE000u); l.y = v.y - h.y;
            h.z = __uint_as_float(__float_as_uint(v.z) & 0xFFFFE000u); l.z = v.z - h.z;
            h.w = __uint_as_float(__float_as_uint(v.w) & 0xFFFFE000u); l.w = v.w - h.w;
            *(float4*)&Bh[kk * BSTR + bn] = h;
            *(float4*)&Bl[kk * BSTR + bn] = l;
        }
        __syncthreads();

#pragma unroll
        for (int ks = 0; ks < GBK; ks += 8) {
            // A fragments (hi and lo) for both 16-row subtiles
            uint32_t ah[2][4], al[2][4];
#pragma unroll
            for (int mt = 0; mt < 2; mt++) {
                int r0 = wm + mt * 16 + g;
                int c0 = ks + tg;
                ah[mt][0] = __float_as_uint(Ah[c0 * ASTR + r0]);
                ah[mt][1] = __float_as_uint(Ah[c0 * ASTR + r0 + 8]);
                ah[mt][2] = __float_as_uint(Ah[(c0 + 4) * ASTR + r0]);
                ah[mt][3] = __float_as_uint(Ah[(c0 + 4) * ASTR + r0 + 8]);
                al[mt][0] = __float_as_uint(Al[c0 * ASTR + r0]);
                al[mt][1] = __float_as_uint(Al[c0 * ASTR + r0 + 8]);
                al[mt][2] = __float_as_uint(Al[(c0 + 4) * ASTR + r0]);
                al[mt][3] = __float_as_uint(Al[(c0 + 4) * ASTR + r0 + 8]);
            }
#pragma unroll
            for (int nt = 0; nt < 8; nt++) {
                int col = wn + nt * 8 + g;
                int kr  = ks + tg;
                uint32_t bh0 = __float_as_uint(Bh[kr * BSTR + col]);
                uint32_t bh1 = __float_as_uint(Bh[(kr + 4) * BSTR + col]);
                uint32_t bl0 = __float_as_uint(Bl[kr * BSTR + col]);
                uint32_t bl1 = __float_as_uint(Bl[(kr + 4) * BSTR + col]);
#pragma unroll
                for (int mt = 0; mt < 2; mt++) {
                    mma_tf32(acc[mt][nt], ah[mt], bh0, bh1);
                    mma_tf32(acc[mt][nt], ah[mt], bl0, bl1);
                    mma_tf32(acc[mt][nt], al[mt], bh0, bh1);
                }
            }
        }
        __syncthreads();
    }

    // ---- epilogue ----
#pragma unroll
    for (int mt = 0; mt < 2; mt++) {
        int row = blockIdx.y * GBM + wm + mt * 16 + g;
#pragma unroll
        for (int nt = 0; nt < 8; nt++) {
            int col = blockIdx.x * GBN + wn + nt * 8 + tg * 2;
            *(float2*)(C + (size_t)row * N + col)       = make_float2(acc[mt][nt][0], acc[mt][nt][1]);
            *(float2*)(C + (size_t)(row + 8) * N + col) = make_float2(acc[mt][nt][2], acc[mt][nt][3]);
        }
    }
}

// ---------------------------------------------------------------------------
// RoPE (unchanged)
// ---------------------------------------------------------------------------
__global__ void rope_kernel(float* __restrict__ x, int heads)
{
    int idx = blockIdx.x * blockDim.x + threadIdx.x;
    int total = TT * heads * 64;
    if (idx >= total) return;
    int j  = idx & 63;
    int th = idx >> 6;
    int h  = th % heads;
    int t  = th / heads;
    int pos = HIST + (t & (QLEN - 1));

    float e = (float)(2 * j) * (1.0f / 128.0f);
    float freq = powf(1.0e6f, -e);
    float ang = (float)pos * freq;
    float s, c;
    sincosf(ang, &s, &c);

    size_t base = (size_t)t * heads * HD + (size_t)h * HD + j;
    float x0 = x[base];
    float x1 = x[base + 64];
    x[base]      = x0 * c - x1 * s;
    x[base + 64] = x1 * c + x0 * s;
}

// ---------------------------------------------------------------------------
// Flash-style attention (unchanged from passing R1 kernel)
// ---------------------------------------------------------------------------
#define ATTN_SMEM_FLOATS (64*129 + 64*129 + 64*128 + 64*65 + 64)
#define ATTN_SMEM_BYTES  (ATTN_SMEM_FLOATS * 4)

__global__ __launch_bounds__(256) void attn_kernel(
    const float* __restrict__ kcache, const float* __restrict__ vcache)
{
    const int i0  = blockIdx.x * 64;
    const int h   = blockIdx.y;
    const int b   = blockIdx.z;
    const int kvh = h >> 2;
    const int tid = threadIdx.x;

    extern __shared__ float sm[];
    float* sQ = sm;
    float* sK = sQ + 64 * 129;
    float* sV = sK + 64 * 129;
    float* sS = sV + 64 * 128;
    float* sA = sS + 64 * 65;

#pragma unroll
    for (int it = 0; it < 8; ++it) {
        int idx = it * 256 + tid;
        int r = idx >> 5;
        int d4 = (idx & 31) * 4;
        float4 v = *(const float4*)&g_q[(size_t)(b * QLEN + i0 + r) * HH + h * HD + d4];
        float* dst = &sQ[r * 129 + d4];
        dst[0] = v.x; dst[1] = v.y; dst[2] = v.z; dst[3] = v.w;
    }

    const int sy = tid >> 4, sx = tid & 15;
    const int row = tid >> 2, l4 = tid & 3;

    float m = -3.0e38f, l = 0.f;
    float o[4][8];
#pragma unroll
    for (int r = 0; r < 4; r++)
#pragma unroll
        for (int c = 0; c < 8; c++) o[r][c] = 0.f;

    const int qpos0 = HIST + i0;

    for (int t = 0; t < 17; ++t) {
        const int p0 = i0 + t * 64;
        __syncthreads();

#pragma unroll
        for (int it = 0; it < 8; ++it) {
            int idx = it * 256 + tid;
            int r = idx >> 5;
            int d4 = (idx & 31) * 4;
            int p = p0 + r;
            const float *src_k, *src_v;
            if (p < HIST) {
                size_t base = ((size_t)(b * KVLEN + p) * NKV + kvh) * HD + d4;
                src_k = kcache + base;
                src_v = vcache + base;
            } else {
                size_t base = (size_t)(b * QLEN + (p - HIST)) * DKV + kvh * HD + d4;
                src_k = g_k + base;
                src_v = g_v + base;
            }
            float4 kv = *(const float4*)src_k;
            float* kd = &sK[r * 129 + d4];
            kd[0] = kv.x; kd[1] = kv.y; kd[2] = kv.z; kd[3] = kv.w;
            *(float4*)&sV[r * 128 + d4] = *(const float4*)src_v;
        }
        __syncthreads();

        float acc[4][4];
#pragma unroll
        for (int r = 0; r < 4; r++)
#pragma unroll
            for (int c = 0; c < 4; c++) acc[r][c] = 0.f;

        for (int kk = 0; kk < 128; ++kk) {
            float ra[4], rb[4];
#pragma unroll
            for (int r = 0; r < 4; r++) ra[r] = sQ[(sy * 4 + r) * 129 + kk];
#pragma unroll
            for (int c = 0; c < 4; c++) rb[c] = sK[(sx * 4 + c) * 129 + kk];
#pragma unroll
            for (int r = 0; r < 4; r++)
#pragma unroll
                for (int c = 0; c < 4; c++)
                    acc[r][c] = fmaf(ra[r], rb[c], acc[r][c]);
        }

#pragma unroll
        for (int r = 0; r < 4; r++) {
            int qp = qpos0 + sy * 4 + r;
#pragma unroll
            for (int c = 0; c < 4; c++) {
                int kp = p0 + sx * 4 + c;
                float s = acc[r][c] * SCALE;
                bool valid = (kp <= qp) && ((qp - kp) < WINDOW);
                sS[(sy * 4 + r) * 65 + sx * 4 + c] = valid ? s : -3.0e38f;
            }
        }
        __syncthreads();

        float tm = -3.0e38f;
#pragma unroll
        for (int j = 0; j < 16; j++) tm = fmaxf(tm, sS[row * 65 + l4 * 16 + j]);
        tm = fmaxf(tm, __shfl_xor_sync(0xffffffffu, tm, 1));
        tm = fmaxf(tm, __shfl_xor_sync(0xffffffffu, tm, 2));
        float mnew = fmaxf(m, tm);
        float alpha = __expf(m - mnew);
        float psum = 0.f;
#pragma unroll
        for (int j = 0; j < 16; j++) {
            float p = __expf(sS[row * 65 + l4 * 16 + j] - mnew);
            sS[row * 65 + l4 * 16 + j] = p;
            psum += p;
        }
        psum += __shfl_xor_sync(0xffffffffu, psum, 1);
        psum += __shfl_xor_sync(0xffffffffu, psum, 2);
        l = l * alpha + psum;
        m = mnew;
        if (l4 == 0) sA[row] = alpha;
        __syncthreads();

#pragma unroll
        for (int r = 0; r < 4; r++) {
            float a = sA[sy * 4 + r];
#pragma unroll
            for (int c = 0; c < 8; c++) o[r][c] *= a;
        }
        for (int j = 0; j < 64; ++j) {
            float p[4];
#pragma unroll
            for (int r = 0; r < 4; r++) p[r] = sS[(sy * 4 + r) * 65 + j];
            float4 v0 = *(float4*)&sV[j * 128 + sx * 8];
            float4 v1 = *(float4*)&sV[j * 128 + sx * 8 + 4];
            float vv[8] = {v0.x, v0.y, v0.z, v0.w, v1.x, v1.y, v1.z, v1.w};
#pragma unroll
            for (int r = 0; r < 4; r++)
#pragma unroll
                for (int c = 0; c < 8; c++)
                    o[r][c] = fmaf(p[r], vv[c], o[r][c]);
        }
    }

    __syncthreads();
    if (l4 == 0) sA[row] = 1.0f / l;
    __syncthreads();
#pragma unroll
    for (int r = 0; r < 4; r++) {
        float inv = sA[sy * 4 + r];
        float* dst = &g_o[(size_t)(b * QLEN + i0 + sy * 4 + r) * HH + h * HD + sx * 8];
#pragma unroll
        for (int c = 0; c < 8; c++) dst[c] = o[r][c] * inv;
    }
}

// ---------------------------------------------------------------------------
// Launch
// ---------------------------------------------------------------------------
extern "C" void kernel_launch(void* const* d_in, const int* in_sizes, int n_in,
                              void* d_out, int out_size)
{
    const float* hs = (const float*)d_in[0];
    const float* wq = (const float*)d_in[1];
    const float* wk = (const float*)d_in[2];
    const float* wv = (const float*)d_in[3];
    const float* wo = (const float*)d_in[4];
    const float* kc = (const float*)d_in[5];
    const float* vc = (const float*)d_in[6];

    float *qb, *kb, *vb, *ob;
    cudaGetSymbolAddress((void**)&qb, g_q);
    cudaGetSymbolAddress((void**)&kb, g_k);
    cudaGetSymbolAddress((void**)&vb, g_v);
    cudaGetSymbolAddress((void**)&ob, g_o);

    cudaFuncSetAttribute(attn_kernel, cudaFuncAttributeMaxDynamicSharedMemorySize,
                         ATTN_SMEM_BYTES);
    cudaFuncSetAttribute(tf32_gemm_kernel, cudaFuncAttributeMaxDynamicSharedMemorySize,
                         GEMM_SMEM_BYTES);

    dim3 gq(HH / GBN, TT / GBM);     // 32 x 32
    dim3 gkv(DKV / GBN, TT / GBM);   // 8 x 32

    tf32_gemm_kernel<<<gq,  256, GEMM_SMEM_BYTES>>>(TT, HH,  HH, hs, wq, qb);
    tf32_gemm_kernel<<<gkv, 256, GEMM_SMEM_BYTES>>>(TT, DKV, HH, hs, wk, kb);
    tf32_gemm_kernel<<<gkv, 256, GEMM_SMEM_BYTES>>>(TT, DKV, HH, hs, wv, vb);

    {
        int totq = TT * NHEADS * 64;
        rope_kernel<<<(totq + 255) / 256, 256>>>(qb, NHEADS);
        int totk = TT * NKV * 64;
        rope_kernel<<<(totk + 255) / 256, 256>>>(kb, NKV);
    }

    dim3 ga(QLEN / 64, NHEADS, BATCH);
    attn_kernel<<<ga, 256, ATTN_SMEM_BYTES>>>(kc, vc);

    tf32_gemm_kernel<<<gq, 256, GEMM_SMEM_BYTES>>>(TT, HH, HH, ob, wo, (float*)d_out);
}